// round 2
// baseline (speedup 1.0000x reference)
#include <cuda_runtime.h>

#define SEQ 2048
#define EMB 2048
#define NHEAD 32
#define HDIM 64
#define SCALING 0.125f

// Scratch buffers (allocation-free rule: __device__ globals)
__device__ float g_Q[SEQ * EMB];
__device__ float g_K[SEQ * EMB];
__device__ float g_V[SEQ * EMB];
__device__ float g_O[SEQ * EMB];

// ---------------------------------------------------------------------------
// GEMM: C[M,N] = (A[M,K] @ B[N,K]^T + bias[N]) * scale
// M = N = K = 2048. 128x128 block tile, BK=16, 256 threads, 8x8 microtile.
// ---------------------------------------------------------------------------
#define BM 128
#define BN 128
#define BK 16
#define GK 2048

__global__ __launch_bounds__(256) void gemm_nt_kernel(
    const float* __restrict__ A, const float* __restrict__ B,
    const float* __restrict__ bias, float* __restrict__ C, float scale)
{
    __shared__ float As[BK][BM];
    __shared__ float Bs[BK][BN];

    const int tid = threadIdx.x;
    const int tx = tid & 15;        // 0..15 (col block)
    const int ty = tid >> 4;        // 0..15 (row block)
    const int m0 = blockIdx.y * BM;
    const int n0 = blockIdx.x * BN;

    float acc[8][8];
#pragma unroll
    for (int i = 0; i < 8; i++)
#pragma unroll
        for (int j = 0; j < 8; j++) acc[i][j] = 0.f;

    for (int kt = 0; kt < GK; kt += BK) {
#pragma unroll
        for (int u = 0; u < 2; u++) {
            int i = tid + u * 256;          // 0..511 float4 slots
            int row = i >> 2;               // 0..127
            int kq = (i & 3) << 2;          // 0,4,8,12
            float4 a = *(const float4*)&A[(size_t)(m0 + row) * GK + kt + kq];
            As[kq + 0][row] = a.x; As[kq + 1][row] = a.y;
            As[kq + 2][row] = a.z; As[kq + 3][row] = a.w;
            float4 b = *(const float4*)&B[(size_t)(n0 + row) * GK + kt + kq];
            Bs[kq + 0][row] = b.x; Bs[kq + 1][row] = b.y;
            Bs[kq + 2][row] = b.z; Bs[kq + 3][row] = b.w;
        }
        __syncthreads();

#pragma unroll
        for (int k = 0; k < BK; k++) {
            float4 a0 = *(const float4*)&As[k][ty * 8];
            float4 a1 = *(const float4*)&As[k][ty * 8 + 4];
            float4 b0 = *(const float4*)&Bs[k][tx * 8];
            float4 b1 = *(const float4*)&Bs[k][tx * 8 + 4];
            float ar[8] = {a0.x, a0.y, a0.z, a0.w, a1.x, a1.y, a1.z, a1.w};
            float br[8] = {b0.x, b0.y, b0.z, b0.w, b1.x, b1.y, b1.z, b1.w};
#pragma unroll
            for (int i = 0; i < 8; i++)
#pragma unroll
                for (int j = 0; j < 8; j++)
                    acc[i][j] += ar[i] * br[j];
        }
        __syncthreads();
    }

    float4 bv0 = *(const float4*)&bias[n0 + tx * 8];
    float4 bv1 = *(const float4*)&bias[n0 + tx * 8 + 4];
    float bb[8] = {bv0.x, bv0.y, bv0.z, bv0.w, bv1.x, bv1.y, bv1.z, bv1.w};

#pragma unroll
    for (int i = 0; i < 8; i++) {
        int row = m0 + ty * 8 + i;
        float4 o0, o1;
        o0.x = (acc[i][0] + bb[0]) * scale;
        o0.y = (acc[i][1] + bb[1]) * scale;
        o0.z = (acc[i][2] + bb[2]) * scale;
        o0.w = (acc[i][3] + bb[3]) * scale;
        o1.x = (acc[i][4] + bb[4]) * scale;
        o1.y = (acc[i][5] + bb[5]) * scale;
        o1.z = (acc[i][6] + bb[6]) * scale;
        o1.w = (acc[i][7] + bb[7]) * scale;
        *(float4*)&C[(size_t)row * GK + n0 + tx * 8] = o0;
        *(float4*)&C[(size_t)row * GK + n0 + tx * 8 + 4] = o1;
    }
}

// ---------------------------------------------------------------------------
// QuotRem fake quantize: groups of 16 contiguous floats (base_gs = r_gs = 16,
// and head dim 64 is a multiple of 16, so flat grouping == per-head grouping).
// q_bits = 1, r_bits = 3 (r_max=3, r_min=-4).
// ---------------------------------------------------------------------------
__global__ __launch_bounds__(256) void quotrem_quantize_kernel(float* __restrict__ X)
{
    const int g = blockIdx.x * blockDim.x + threadIdx.x;
    if (g >= (SEQ * EMB) / 16) return;

    float4* p = (float4*)(X + (size_t)g * 16);
    float4 a = p[0], b = p[1], c = p[2], d = p[3];
    float x[16] = {a.x, a.y, a.z, a.w, b.x, b.y, b.z, b.w,
                   c.x, c.y, c.z, c.w, d.x, d.y, d.z, d.w};

    float mx = x[0], mn = x[0];
#pragma unroll
    for (int i = 1; i < 16; i++) {
        mx = fmaxf(mx, x[i]);
        mn = fminf(mn, x[i]);
    }
    float ma = fmaxf(fmaxf(mx, -mn), 1e-8f);

    float l2 = log2f(ma);
    float bflo = exp2f(floorf(l2));
    float bcei = exp2f(ceilf(l2));
    float base = (fabsf(ma - bflo) <= fabsf(bcei - ma)) ? bflo : bcei;
    base = fminf(fmaxf(base, 1.0f), 128.0f);

    float sign = (fabsf(mx) >= fabsf(mn)) ? 1.0f : -1.0f;
    float hb = 0.5f * base;
    float sb = sign * base;

    float qs[16], r[16];
    float mar = 0.f;
#pragma unroll
    for (int i = 0; i < 16; i++) {
        float q = (x[i] * sign >= hb) ? 1.0f : 0.0f;
        qs[i] = q * sb;
        r[i] = x[i] - qs[i];
        mar = fmaxf(mar, fabsf(r[i]));
    }
    mar = fmaxf(mar, 1e-8f);
    float sr = mar * (1.0f / 3.0f);   // scale_r = max_abs_r / r_max

#pragma unroll
    for (int i = 0; i < 16; i++) {
        float rq = rintf(r[i] / sr);           // half-to-even, matches jnp.round
        rq = fminf(fmaxf(rq, -4.0f), 3.0f);    // clip [r_min, r_max]
        x[i] = qs[i] + rq * sr;
    }

    a.x = x[0];  a.y = x[1];  a.z = x[2];  a.w = x[3];
    b.x = x[4];  b.y = x[5];  b.z = x[6];  b.w = x[7];
    c.x = x[8];  c.y = x[9];  c.z = x[10]; c.w = x[11];
    d.x = x[12]; d.y = x[13]; d.z = x[14]; d.w = x[15];
    p[0] = a; p[1] = b; p[2] = c; p[3] = d;
}

// ---------------------------------------------------------------------------
// Causal flash attention. One thread per query row; 128 rows per block.
// K/V staged through SMEM in 64-key tiles (broadcast reads). Online softmax
// with rare-branch running-max update. Q is pre-scaled by 1/sqrt(HD).
// ---------------------------------------------------------------------------
#define PROC_KEY(JJ) do {                                                     \
    const float4* kp = (const float4*)&Ks[(JJ)][0];                           \
    float s = 0.f;                                                            \
    _Pragma("unroll")                                                         \
    for (int dq = 0; dq < 16; dq++) {                                         \
        float4 kv = kp[dq];                                                   \
        s += q[4*dq+0]*kv.x + q[4*dq+1]*kv.y                                  \
           + q[4*dq+2]*kv.z + q[4*dq+3]*kv.w;                                 \
    }                                                                         \
    const float4* vp = (const float4*)&Vs[(JJ)][0];                           \
    if (s <= m) {                                                             \
        float pw = __expf(s - m);                                             \
        l += pw;                                                              \
        _Pragma("unroll")                                                     \
        for (int dq = 0; dq < 16; dq++) {                                     \
            float4 vv = vp[dq];                                               \
            o[4*dq+0] += pw * vv.x; o[4*dq+1] += pw * vv.y;                   \
            o[4*dq+2] += pw * vv.z; o[4*dq+3] += pw * vv.w;                   \
        }                                                                     \
    } else {                                                                  \
        float cf = __expf(m - s);                                             \
        m = s; l = l * cf + 1.0f;                                             \
        _Pragma("unroll")                                                     \
        for (int dq = 0; dq < 16; dq++) {                                     \
            float4 vv = vp[dq];                                               \
            o[4*dq+0] = o[4*dq+0]*cf + vv.x; o[4*dq+1] = o[4*dq+1]*cf + vv.y; \
            o[4*dq+2] = o[4*dq+2]*cf + vv.z; o[4*dq+3] = o[4*dq+3]*cf + vv.w; \
        }                                                                     \
    }                                                                         \
} while (0)

__global__ __launch_bounds__(128) void flash_attn_kernel(
    const float* __restrict__ Q, const float* __restrict__ K,
    const float* __restrict__ V, float* __restrict__ O)
{
    __shared__ float Ks[64][64];
    __shared__ float Vs[64][64];

    const int h = blockIdx.y;
    const int r0 = blockIdx.x * 128;
    const int tid = threadIdx.x;
    const int row = r0 + tid;
    const int hb = h * HDIM;

    float q[64], o[64];
    const float4* qp = (const float4*)&Q[(size_t)row * EMB + hb];
#pragma unroll
    for (int i = 0; i < 16; i++) {
        float4 t = qp[i];
        q[4*i+0] = t.x; q[4*i+1] = t.y; q[4*i+2] = t.z; q[4*i+3] = t.w;
        o[4*i+0] = 0.f; o[4*i+1] = 0.f; o[4*i+2] = 0.f; o[4*i+3] = 0.f;
    }
    float m = -1e30f, l = 0.f;

    const int ntiles = 2 * blockIdx.x + 2;    // keys 0 .. r0+127
    for (int t = 0; t < ntiles; t++) {
        const int c0 = t * 64;
        __syncthreads();
#pragma unroll
        for (int u = 0; u < 8; u++) {
            int i = tid + u * 128;            // 0..1023 float4 slots
            int kr = i >> 4;                  // key row 0..63
            int cc = (i & 15) << 2;           // float offset
            ((float4*)&Ks[kr][cc])[0] =
                *(const float4*)&K[(size_t)(c0 + kr) * EMB + hb + cc];
            ((float4*)&Vs[kr][cc])[0] =
                *(const float4*)&V[(size_t)(c0 + kr) * EMB + hb + cc];
        }
        __syncthreads();

        const bool full = (c0 + 63 <= r0);
        if (full) {
#pragma unroll 4
            for (int j = 0; j < 64; j++) { PROC_KEY(j); }
        } else {
            int jmax = row - c0 + 1;
            if (jmax > 64) jmax = 64;
            for (int j = 0; j < jmax; j++) { PROC_KEY(j); }
        }
    }

    const float invl = 1.0f / l;
    float4* op = (float4*)&O[(size_t)row * EMB + hb];
#pragma unroll
    for (int i = 0; i < 16; i++) {
        float4 t;
        t.x = o[4*i+0] * invl; t.y = o[4*i+1] * invl;
        t.z = o[4*i+2] * invl; t.w = o[4*i+3] * invl;
        op[i] = t;
    }
}

// ---------------------------------------------------------------------------
// Launch
// ---------------------------------------------------------------------------
extern "C" void kernel_launch(void* const* d_in, const int* in_sizes, int n_in,
                              void* d_out, int out_size)
{
    const float* X  = (const float*)d_in[0];
    const float* Wq = (const float*)d_in[1];
    const float* bq = (const float*)d_in[2];
    const float* Wk = (const float*)d_in[3];
    const float* bk = (const float*)d_in[4];
    const float* Wv = (const float*)d_in[5];
    const float* bv = (const float*)d_in[6];
    const float* Wo = (const float*)d_in[7];
    const float* bo = (const float*)d_in[8];
    float* out = (float*)d_out;

    void *pQ, *pK, *pV, *pO;
    cudaGetSymbolAddress(&pQ, g_Q);
    cudaGetSymbolAddress(&pK, g_K);
    cudaGetSymbolAddress(&pV, g_V);
    cudaGetSymbolAddress(&pO, g_O);
    float* Qb = (float*)pQ;
    float* Kb = (float*)pK;
    float* Vb = (float*)pV;
    float* Ob = (float*)pO;

    dim3 gg(EMB / BN, SEQ / BM);
    dim3 gb(256);

    gemm_nt_kernel<<<gg, gb>>>(X, Wq, bq, Qb, SCALING);
    gemm_nt_kernel<<<gg, gb>>>(X, Wk, bk, Kb, 1.0f);
    gemm_nt_kernel<<<gg, gb>>>(X, Wv, bv, Vb, 1.0f);

    const int ngroups = (SEQ * EMB) / 16;
    quotrem_quantize_kernel<<<ngroups / 256, 256>>>(Kb);
    quotrem_quantize_kernel<<<ngroups / 256, 256>>>(Vb);

    flash_attn_kernel<<<dim3(SEQ / 128, NHEAD), 128>>>(Qb, Kb, Vb, Ob);

    gemm_nt_kernel<<<gg, gb>>>(Ob, Wo, bo, out, 1.0f);
}

// round 6
// speedup vs baseline: 1.1045x; 1.1045x over previous
#include <cuda_runtime.h>
#include <cuda_bf16.h>

#define SEQ 2048
#define EMB 2048
#define NHEAD 32
#define HDIM 64
#define SCALING 0.125f

// Scratch buffers (allocation-free rule: __device__ globals)
__device__ float g_Q[SEQ * EMB];
__device__ float g_K[SEQ * EMB];
__device__ float g_V[SEQ * EMB];
__device__ float g_O[SEQ * EMB];

// ---------------------------------------------------------------------------
// helpers
// ---------------------------------------------------------------------------
__device__ __forceinline__ unsigned s2u(const void* p) {
    unsigned a;
    asm("{ .reg .u64 t; cvta.to.shared.u64 t, %1; cvt.u32.u64 %0, t; }"
        : "=r"(a) : "l"(p));
    return a;
}

// fp32 -> (tf32 hi, tf32 lo) : hi = rna_tf32(x), lo = rna_tf32(x - hi)
__device__ __forceinline__ void tf32split(float x, unsigned& hi, unsigned& lo) {
    unsigned h;
    asm("cvt.rna.tf32.f32 %0, %1;" : "=r"(h) : "f"(x));
    float r = x - __uint_as_float(h);
    asm("cvt.rna.tf32.f32 %0, %1;" : "=r"(lo) : "f"(r));
    hi = h;
}

#define MMA_TF32(C0, C1, C2, C3, A0, A1, A2, A3, B0, B1)                      \
    asm volatile(                                                             \
        "mma.sync.aligned.m16n8k8.row.col.f32.tf32.tf32.f32 "                 \
        "{%0,%1,%2,%3}, {%4,%5,%6,%7}, {%8,%9}, {%0,%1,%2,%3};"               \
        : "+f"(C0), "+f"(C1), "+f"(C2), "+f"(C3)                              \
        : "r"(A0), "r"(A1), "r"(A2), "r"(A3), "r"(B0), "r"(B1))

#define LDSM_X4(R0, R1, R2, R3, ADDR)                                         \
    asm volatile("ldmatrix.sync.aligned.m8n8.x4.shared.b16 {%0,%1,%2,%3}, [%4];" \
        : "=r"(R0), "=r"(R1), "=r"(R2), "=r"(R3) : "r"(ADDR))

#define LDSM_X2(R0, R1, ADDR)                                                 \
    asm volatile("ldmatrix.sync.aligned.m8n8.x2.shared.b16 {%0,%1}, [%2];"    \
        : "=r"(R0), "=r"(R1) : "r"(ADDR))

// ---------------------------------------------------------------------------
// 3xTF32 GEMM via mma.sync: C[M,N] = (A[M,K] @ B[N,K]^T + bias[N]) * scale
// Used ONLY for Q projection and output projection (smooth downstream paths).
// ---------------------------------------------------------------------------
#define ROW_B 144
#define TILE_B (128 * ROW_B)
#define STAGE_B (4 * TILE_B)
#define GEMM_SMEM (2 * STAGE_B)
#define NCH 64

__global__ __launch_bounds__(256, 1)
void gemm_mma_kernel(const float* __restrict__ A, const float* __restrict__ B,
                     const float* __restrict__ bias, float* __restrict__ C,
                     float scale)
{
    extern __shared__ char smem[];
    const unsigned sb = s2u(smem);
    const int tid = threadIdx.x;
    const int wid = tid >> 5;
    const int lane = tid & 31;
    const int wm = wid & 1;
    const int wn = wid >> 1;
    const int m0 = blockIdx.y * 128;
    const int n0 = blockIdx.x * 128;

    float acc[4][4][4];
#pragma unroll
    for (int i = 0; i < 4; i++)
#pragma unroll
        for (int j = 0; j < 4; j++)
#pragma unroll
            for (int r = 0; r < 4; r++) acc[i][j][r] = 0.f;

    float4 fa[4], fb[4];

    auto fetch = [&](int c) {
        const int k0 = c * 32;
#pragma unroll
        for (int u = 0; u < 4; u++) {
            int slot = tid + u * 256;
            int row = slot >> 3;
            int kq = (slot & 7) << 2;
            fa[u] = *(const float4*)&A[(size_t)(m0 + row) * EMB + k0 + kq];
            fb[u] = *(const float4*)&B[(size_t)(n0 + row) * EMB + k0 + kq];
        }
    };

    auto store_stage = [&](int s) {
        const unsigned base = sb + (unsigned)s * STAGE_B;
#pragma unroll
        for (int u = 0; u < 4; u++) {
            int slot = tid + u * 256;
            int row = slot >> 3;
            int kq = (slot & 7) << 2;
            unsigned off = (unsigned)(row * ROW_B + kq * 4);
            unsigned h0, h1, h2, h3, l0, l1, l2, l3;
            tf32split(fa[u].x, h0, l0); tf32split(fa[u].y, h1, l1);
            tf32split(fa[u].z, h2, l2); tf32split(fa[u].w, h3, l3);
            asm volatile("st.shared.v4.b32 [%0], {%1,%2,%3,%4};"
                         :: "r"(base + off), "r"(h0), "r"(h1), "r"(h2), "r"(h3) : "memory");
            asm volatile("st.shared.v4.b32 [%0], {%1,%2,%3,%4};"
                         :: "r"(base + TILE_B + off), "r"(l0), "r"(l1), "r"(l2), "r"(l3) : "memory");
            tf32split(fb[u].x, h0, l0); tf32split(fb[u].y, h1, l1);
            tf32split(fb[u].z, h2, l2); tf32split(fb[u].w, h3, l3);
            asm volatile("st.shared.v4.b32 [%0], {%1,%2,%3,%4};"
                         :: "r"(base + 2 * TILE_B + off), "r"(h0), "r"(h1), "r"(h2), "r"(h3) : "memory");
            asm volatile("st.shared.v4.b32 [%0], {%1,%2,%3,%4};"
                         :: "r"(base + 3 * TILE_B + off), "r"(l0), "r"(l1), "r"(l2), "r"(l3) : "memory");
        }
    };

    const unsigned a_rl = (unsigned)((lane & 7) + ((lane >> 3) & 1) * 8);
    const unsigned a_by = (unsigned)((lane >> 4) * 16);
    const unsigned b_rl = (unsigned)(lane & 7);
    const unsigned b_by = (unsigned)(((lane >> 3) & 1) * 16);

    fetch(0);
    store_stage(0);
    __syncthreads();

#pragma unroll 1
    for (int c = 0; c < NCH; c++) {
        if (c + 1 < NCH) fetch(c + 1);

        const unsigned abase = sb + (unsigned)(c & 1) * STAGE_B;
        const unsigned bbase = abase + 2 * TILE_B;

#pragma unroll
        for (int k8 = 0; k8 < 4; k8++) {
            const unsigned koff = (unsigned)(k8 * 32);
            unsigned Ah[4][4], Al[4][4], Bh[4][2], Bl[4][2];
#pragma unroll
            for (int mt = 0; mt < 4; mt++) {
                unsigned ad = abase + (wm * 64 + mt * 16 + a_rl) * ROW_B + a_by + koff;
                LDSM_X4(Ah[mt][0], Ah[mt][1], Ah[mt][2], Ah[mt][3], ad);
                LDSM_X4(Al[mt][0], Al[mt][1], Al[mt][2], Al[mt][3], ad + TILE_B);
            }
#pragma unroll
            for (int nt = 0; nt < 4; nt++) {
                unsigned bd = bbase + (wn * 32 + nt * 8 + b_rl) * ROW_B + b_by + koff;
                LDSM_X2(Bh[nt][0], Bh[nt][1], bd);
                LDSM_X2(Bl[nt][0], Bl[nt][1], bd + TILE_B);
            }
#pragma unroll
            for (int mt = 0; mt < 4; mt++)
#pragma unroll
                for (int nt = 0; nt < 4; nt++) {
                    float* cc = acc[mt][nt];
                    MMA_TF32(cc[0], cc[1], cc[2], cc[3],
                             Ah[mt][0], Ah[mt][1], Ah[mt][2], Ah[mt][3],
                             Bh[nt][0], Bh[nt][1]);
                    MMA_TF32(cc[0], cc[1], cc[2], cc[3],
                             Ah[mt][0], Ah[mt][1], Ah[mt][2], Ah[mt][3],
                             Bl[nt][0], Bl[nt][1]);
                    MMA_TF32(cc[0], cc[1], cc[2], cc[3],
                             Al[mt][0], Al[mt][1], Al[mt][2], Al[mt][3],
                             Bh[nt][0], Bh[nt][1]);
                }
        }
        __syncthreads();
        if (c + 1 < NCH) {
            store_stage((c + 1) & 1);
            __syncthreads();
        }
    }

    const int g = lane >> 2;
    const int c2 = (lane & 3) * 2;
#pragma unroll
    for (int mt = 0; mt < 4; mt++) {
        const int r0 = m0 + wm * 64 + mt * 16 + g;
#pragma unroll
        for (int nt = 0; nt < 4; nt++) {
            const int col = n0 + wn * 32 + nt * 8 + c2;
            float2 bv = *(const float2*)&bias[col];
            float2 o0, o1;
            o0.x = (acc[mt][nt][0] + bv.x) * scale;
            o0.y = (acc[mt][nt][1] + bv.y) * scale;
            o1.x = (acc[mt][nt][2] + bv.x) * scale;
            o1.y = (acc[mt][nt][3] + bv.y) * scale;
            *(float2*)&C[(size_t)r0 * EMB + col] = o0;
            *(float2*)&C[(size_t)(r0 + 8) * EMB + col] = o1;
        }
    }
}

// ---------------------------------------------------------------------------
// fp32 SIMT GEMM (VERIFIED in round 2) — used for K and V projections, which
// feed the hypersensitive QuotRem quantizer.
// ---------------------------------------------------------------------------
#define BM 128
#define BN 128
#define BK 16
#define GK 2048

__global__ __launch_bounds__(256) void gemm_nt_kernel(
    const float* __restrict__ A, const float* __restrict__ B,
    const float* __restrict__ bias, float* __restrict__ C, float scale)
{
    __shared__ float As[BK][BM];
    __shared__ float Bs[BK][BN];

    const int tid = threadIdx.x;
    const int tx = tid & 15;
    const int ty = tid >> 4;
    const int m0 = blockIdx.y * BM;
    const int n0 = blockIdx.x * BN;

    float acc[8][8];
#pragma unroll
    for (int i = 0; i < 8; i++)
#pragma unroll
        for (int j = 0; j < 8; j++) acc[i][j] = 0.f;

    for (int kt = 0; kt < GK; kt += BK) {
#pragma unroll
        for (int u = 0; u < 2; u++) {
            int i = tid + u * 256;
            int row = i >> 2;
            int kq = (i & 3) << 2;
            float4 a = *(const float4*)&A[(size_t)(m0 + row) * GK + kt + kq];
            As[kq + 0][row] = a.x; As[kq + 1][row] = a.y;
            As[kq + 2][row] = a.z; As[kq + 3][row] = a.w;
            float4 b = *(const float4*)&B[(size_t)(n0 + row) * GK + kt + kq];
            Bs[kq + 0][row] = b.x; Bs[kq + 1][row] = b.y;
            Bs[kq + 2][row] = b.z; Bs[kq + 3][row] = b.w;
        }
        __syncthreads();

#pragma unroll
        for (int k = 0; k < BK; k++) {
            float4 a0 = *(const float4*)&As[k][ty * 8];
            float4 a1 = *(const float4*)&As[k][ty * 8 + 4];
            float4 b0 = *(const float4*)&Bs[k][tx * 8];
            float4 b1 = *(const float4*)&Bs[k][tx * 8 + 4];
            float ar[8] = {a0.x, a0.y, a0.z, a0.w, a1.x, a1.y, a1.z, a1.w};
            float br[8] = {b0.x, b0.y, b0.z, b0.w, b1.x, b1.y, b1.z, b1.w};
#pragma unroll
            for (int i = 0; i < 8; i++)
#pragma unroll
                for (int j = 0; j < 8; j++)
                    acc[i][j] += ar[i] * br[j];
        }
        __syncthreads();
    }

    float4 bv0 = *(const float4*)&bias[n0 + tx * 8];
    float4 bv1 = *(const float4*)&bias[n0 + tx * 8 + 4];
    float bb[8] = {bv0.x, bv0.y, bv0.z, bv0.w, bv1.x, bv1.y, bv1.z, bv1.w};

#pragma unroll
    for (int i = 0; i < 8; i++) {
        int row = m0 + ty * 8 + i;
        float4 o0, o1;
        o0.x = (acc[i][0] + bb[0]) * scale;
        o0.y = (acc[i][1] + bb[1]) * scale;
        o0.z = (acc[i][2] + bb[2]) * scale;
        o0.w = (acc[i][3] + bb[3]) * scale;
        o1.x = (acc[i][4] + bb[4]) * scale;
        o1.y = (acc[i][5] + bb[5]) * scale;
        o1.z = (acc[i][6] + bb[6]) * scale;
        o1.w = (acc[i][7] + bb[7]) * scale;
        *(float4*)&C[(size_t)row * GK + n0 + tx * 8] = o0;
        *(float4*)&C[(size_t)row * GK + n0 + tx * 8 + 4] = o1;
    }
}

// ---------------------------------------------------------------------------
// QuotRem fake quantize (verified)
// ---------------------------------------------------------------------------
__global__ __launch_bounds__(256) void quotrem_quantize_kernel(float* __restrict__ X)
{
    const int g = blockIdx.x * blockDim.x + threadIdx.x;
    if (g >= (SEQ * EMB) / 16) return;

    float4* p = (float4*)(X + (size_t)g * 16);
    float4 a = p[0], b = p[1], c = p[2], d = p[3];
    float x[16] = {a.x, a.y, a.z, a.w, b.x, b.y, b.z, b.w,
                   c.x, c.y, c.z, c.w, d.x, d.y, d.z, d.w};

    float mx = x[0], mn = x[0];
#pragma unroll
    for (int i = 1; i < 16; i++) {
        mx = fmaxf(mx, x[i]);
        mn = fminf(mn, x[i]);
    }
    float ma = fmaxf(fmaxf(mx, -mn), 1e-8f);

    float l2 = log2f(ma);
    float bflo = exp2f(floorf(l2));
    float bcei = exp2f(ceilf(l2));
    float base = (fabsf(ma - bflo) <= fabsf(bcei - ma)) ? bflo : bcei;
    base = fminf(fmaxf(base, 1.0f), 128.0f);

    float sign = (fabsf(mx) >= fabsf(mn)) ? 1.0f : -1.0f;
    float hb = 0.5f * base;
    float sb = sign * base;

    float qs[16], r[16];
    float mar = 0.f;
#pragma unroll
    for (int i = 0; i < 16; i++) {
        float q = (x[i] * sign >= hb) ? 1.0f : 0.0f;
        qs[i] = q * sb;
        r[i] = x[i] - qs[i];
        mar = fmaxf(mar, fabsf(r[i]));
    }
    mar = fmaxf(mar, 1e-8f);
    float sr = mar * (1.0f / 3.0f);

#pragma unroll
    for (int i = 0; i < 16; i++) {
        float rq = rintf(r[i] / sr);
        rq = fminf(fmaxf(rq, -4.0f), 3.0f);
        x[i] = qs[i] + rq * sr;
    }

    a.x = x[0];  a.y = x[1];  a.z = x[2];  a.w = x[3];
    b.x = x[4];  b.y = x[5];  b.z = x[6];  b.w = x[7];
    c.x = x[8];  c.y = x[9];  c.z = x[10]; c.w = x[11];
    d.x = x[12]; d.y = x[13]; d.z = x[14]; d.w = x[15];
    p[0] = a; p[1] = b; p[2] = c; p[3] = d;
}

// ---------------------------------------------------------------------------
// Causal flash attention (verified)
// ---------------------------------------------------------------------------
#define PROC_KEY(JJ) do {                                                     \
    const float4* kp = (const float4*)&Ks[(JJ)][0];                           \
    float s = 0.f;                                                            \
    _Pragma("unroll")                                                         \
    for (int dq = 0; dq < 16; dq++) {                                         \
        float4 kv = kp[dq];                                                   \
        s += q[4*dq+0]*kv.x + q[4*dq+1]*kv.y                                  \
           + q[4*dq+2]*kv.z + q[4*dq+3]*kv.w;                                 \
    }                                                                         \
    const float4* vp = (const float4*)&Vs[(JJ)][0];                           \
    if (s <= m) {                                                             \
        float pw = __expf(s - m);                                             \
        l += pw;                                                              \
        _Pragma("unroll")                                                     \
        for (int dq = 0; dq < 16; dq++) {                                     \
            float4 vv = vp[dq];                                               \
            o[4*dq+0] += pw * vv.x; o[4*dq+1] += pw * vv.y;                   \
            o[4*dq+2] += pw * vv.z; o[4*dq+3] += pw * vv.w;                   \
        }                                                                     \
    } else {                                                                  \
        float cf = __expf(m - s);                                             \
        m = s; l = l * cf + 1.0f;                                             \
        _Pragma("unroll")                                                     \
        for (int dq = 0; dq < 16; dq++) {                                     \
            float4 vv = vp[dq];                                               \
            o[4*dq+0] = o[4*dq+0]*cf + vv.x; o[4*dq+1] = o[4*dq+1]*cf + vv.y; \
            o[4*dq+2] = o[4*dq+2]*cf + vv.z; o[4*dq+3] = o[4*dq+3]*cf + vv.w; \
        }                                                                     \
    }                                                                         \
} while (0)

__global__ __launch_bounds__(128) void flash_attn_kernel(
    const float* __restrict__ Q, const float* __restrict__ K,
    const float* __restrict__ V, float* __restrict__ O)
{
    __shared__ float Ks[64][64];
    __shared__ float Vs[64][64];

    const int h = blockIdx.y;
    const int r0 = blockIdx.x * 128;
    const int tid = threadIdx.x;
    const int row = r0 + tid;
    const int hb = h * HDIM;

    float q[64], o[64];
    const float4* qp = (const float4*)&Q[(size_t)row * EMB + hb];
#pragma unroll
    for (int i = 0; i < 16; i++) {
        float4 t = qp[i];
        q[4*i+0] = t.x; q[4*i+1] = t.y; q[4*i+2] = t.z; q[4*i+3] = t.w;
        o[4*i+0] = 0.f; o[4*i+1] = 0.f; o[4*i+2] = 0.f; o[4*i+3] = 0.f;
    }
    float m = -1e30f, l = 0.f;

    const int ntiles = 2 * blockIdx.x + 2;
    for (int t = 0; t < ntiles; t++) {
        const int c0 = t * 64;
        __syncthreads();
#pragma unroll
        for (int u = 0; u < 8; u++) {
            int i = tid + u * 128;
            int kr = i >> 4;
            int cc = (i & 15) << 2;
            ((float4*)&Ks[kr][cc])[0] =
                *(const float4*)&K[(size_t)(c0 + kr) * EMB + hb + cc];
            ((float4*)&Vs[kr][cc])[0] =
                *(const float4*)&V[(size_t)(c0 + kr) * EMB + hb + cc];
        }
        __syncthreads();

        const bool full = (c0 + 63 <= r0);
        if (full) {
#pragma unroll 4
            for (int j = 0; j < 64; j++) { PROC_KEY(j); }
        } else {
            int jmax = row - c0 + 1;
            if (jmax > 64) jmax = 64;
            for (int j = 0; j < jmax; j++) { PROC_KEY(j); }
        }
    }

    const float invl = 1.0f / l;
    float4* op = (float4*)&O[(size_t)row * EMB + hb];
#pragma unroll
    for (int i = 0; i < 16; i++) {
        float4 t;
        t.x = o[4*i+0] * invl; t.y = o[4*i+1] * invl;
        t.z = o[4*i+2] * invl; t.w = o[4*i+3] * invl;
        op[i] = t;
    }
}

// ---------------------------------------------------------------------------
// Launch
// ---------------------------------------------------------------------------
extern "C" void kernel_launch(void* const* d_in, const int* in_sizes, int n_in,
                              void* d_out, int out_size)
{
    const float* X  = (const float*)d_in[0];
    const float* Wq = (const float*)d_in[1];
    const float* bq = (const float*)d_in[2];
    const float* Wk = (const float*)d_in[3];
    const float* bk = (const float*)d_in[4];
    const float* Wv = (const float*)d_in[5];
    const float* bv = (const float*)d_in[6];
    const float* Wo = (const float*)d_in[7];
    const float* bo = (const float*)d_in[8];
    float* out = (float*)d_out;

    void *pQ, *pK, *pV, *pO;
    cudaGetSymbolAddress(&pQ, g_Q);
    cudaGetSymbolAddress(&pK, g_K);
    cudaGetSymbolAddress(&pV, g_V);
    cudaGetSymbolAddress(&pO, g_O);
    float* Qb = (float*)pQ;
    float* Kb = (float*)pK;
    float* Vb = (float*)pV;
    float* Ob = (float*)pO;

    cudaFuncSetAttribute(gemm_mma_kernel,
                         cudaFuncAttributeMaxDynamicSharedMemorySize, GEMM_SMEM);

    dim3 gg(EMB / 128, SEQ / 128);

    // Q projection: tf32-mma (downstream = smooth softmax path)
    gemm_mma_kernel<<<gg, 256, GEMM_SMEM>>>(X, Wq, bq, Qb, SCALING);
    // K, V projections: exact fp32 (downstream = hypersensitive quantizer)
    gemm_nt_kernel<<<gg, 256>>>(X, Wk, bk, Kb, 1.0f);
    gemm_nt_kernel<<<gg, 256>>>(X, Wv, bv, Vb, 1.0f);

    const int ngroups = (SEQ * EMB) / 16;
    quotrem_quantize_kernel<<<ngroups / 256, 256>>>(Kb);
    quotrem_quantize_kernel<<<ngroups / 256, 256>>>(Vb);

    flash_attn_kernel<<<dim3(SEQ / 128, NHEAD), 128>>>(Qb, Kb, Vb, Ob);

    // Output projection: tf32-mma (directly measured, smooth)
    gemm_mma_kernel<<<gg, 256, GEMM_SMEM>>>(Ob, Wo, bo, out, 1.0f);
}

// round 7
// speedup vs baseline: 1.6428x; 1.4873x over previous
#include <cuda_runtime.h>
#include <cuda_bf16.h>

#define SEQ 2048
#define EMB 2048
#define NHEAD 32
#define HDIM 64
#define SCALING 0.125f

// Scratch buffers (allocation-free rule: __device__ globals)
__device__ float g_Q[SEQ * EMB];
__device__ float g_K[SEQ * EMB];
__device__ float g_V[SEQ * EMB];
__device__ float g_O[SEQ * EMB];

// ---------------------------------------------------------------------------
// helpers
// ---------------------------------------------------------------------------
__device__ __forceinline__ unsigned s2u(const void* p) {
    unsigned a;
    asm("{ .reg .u64 t; cvta.to.shared.u64 t, %1; cvt.u32.u64 %0, t; }"
        : "=r"(a) : "l"(p));
    return a;
}

// fp32 -> (tf32 hi, tf32 lo)
__device__ __forceinline__ void tf32split(float x, unsigned& hi, unsigned& lo) {
    unsigned h;
    asm("cvt.rna.tf32.f32 %0, %1;" : "=r"(h) : "f"(x));
    float r = x - __uint_as_float(h);
    asm("cvt.rna.tf32.f32 %0, %1;" : "=r"(lo) : "f"(r));
    hi = h;
}

// fp32 pair -> packed bf16x2 hi + packed bf16x2 residual (low half = a)
__device__ __forceinline__ void split2(float a, float b, unsigned& hi, unsigned& lo) {
    unsigned h;
    asm("cvt.rn.bf16x2.f32 %0, %1, %2;" : "=r"(h) : "f"(b), "f"(a));
    float ah = __uint_as_float(h << 16);
    float bh = __uint_as_float(h & 0xFFFF0000u);
    float ra = a - ah;
    float rb = b - bh;
    unsigned l;
    asm("cvt.rn.bf16x2.f32 %0, %1, %2;" : "=r"(l) : "f"(rb), "f"(ra));
    hi = h; lo = l;
}

#define MMA_TF32(C0, C1, C2, C3, A0, A1, A2, A3, B0, B1)                      \
    asm volatile(                                                             \
        "mma.sync.aligned.m16n8k8.row.col.f32.tf32.tf32.f32 "                 \
        "{%0,%1,%2,%3}, {%4,%5,%6,%7}, {%8,%9}, {%0,%1,%2,%3};"               \
        : "+f"(C0), "+f"(C1), "+f"(C2), "+f"(C3)                              \
        : "r"(A0), "r"(A1), "r"(A2), "r"(A3), "r"(B0), "r"(B1))

#define MMA_BF16(C0, C1, C2, C3, A0, A1, A2, A3, B0, B1)                      \
    asm volatile(                                                             \
        "mma.sync.aligned.m16n8k16.row.col.f32.bf16.bf16.f32 "                \
        "{%0,%1,%2,%3}, {%4,%5,%6,%7}, {%8,%9}, {%0,%1,%2,%3};"               \
        : "+f"(C0), "+f"(C1), "+f"(C2), "+f"(C3)                              \
        : "r"(A0), "r"(A1), "r"(A2), "r"(A3), "r"(B0), "r"(B1))

#define LDSM_X4(R0, R1, R2, R3, ADDR)                                         \
    asm volatile("ldmatrix.sync.aligned.m8n8.x4.shared.b16 {%0,%1,%2,%3}, [%4];" \
        : "=r"(R0), "=r"(R1), "=r"(R2), "=r"(R3) : "r"(ADDR))

#define LDSM_X2(R0, R1, ADDR)                                                 \
    asm volatile("ldmatrix.sync.aligned.m8n8.x2.shared.b16 {%0,%1}, [%2];"    \
        : "=r"(R0), "=r"(R1) : "r"(ADDR))

#define LDSM_X2_T(R0, R1, ADDR)                                               \
    asm volatile("ldmatrix.sync.aligned.m8n8.x2.trans.shared.b16 {%0,%1}, [%2];" \
        : "=r"(R0), "=r"(R1) : "r"(ADDR))

#define STS_V2(ADDR, V0, V1)                                                  \
    asm volatile("st.shared.v2.b32 [%0], {%1,%2};" :: "r"(ADDR), "r"(V0), "r"(V1) : "memory")

#define STS_V4(ADDR, V0, V1, V2, V3)                                          \
    asm volatile("st.shared.v4.b32 [%0], {%1,%2,%3,%4};"                      \
        :: "r"(ADDR), "r"(V0), "r"(V1), "r"(V2), "r"(V3) : "memory")

// ---------------------------------------------------------------------------
// 3xTF32 GEMM via mma.sync (numerically VERIFIED round 6).
// Used for Q projection + output projection (smooth downstream paths).
// Single-sync double-buffer: sync; store(c+1); fetch(c+2); compute(c).
// ---------------------------------------------------------------------------
#define ROW_B 144
#define TILE_B (128 * ROW_B)
#define STAGE_B (4 * TILE_B)
#define GEMM_SMEM (2 * STAGE_B)
#define NCH 64

__global__ __launch_bounds__(256, 1)
void gemm_mma_kernel(const float* __restrict__ A, const float* __restrict__ B,
                     const float* __restrict__ bias, float* __restrict__ C,
                     float scale)
{
    extern __shared__ char smem[];
    const unsigned sb = s2u(smem);
    const int tid = threadIdx.x;
    const int wid = tid >> 5;
    const int lane = tid & 31;
    const int wm = wid & 1;
    const int wn = wid >> 1;
    const int m0 = blockIdx.y * 128;
    const int n0 = blockIdx.x * 128;

    float acc[4][4][4];
#pragma unroll
    for (int i = 0; i < 4; i++)
#pragma unroll
        for (int j = 0; j < 4; j++)
#pragma unroll
            for (int r = 0; r < 4; r++) acc[i][j][r] = 0.f;

    float4 fa[4], fb[4];

    auto fetch = [&](int c) {
        const int k0 = c * 32;
#pragma unroll
        for (int u = 0; u < 4; u++) {
            int slot = tid + u * 256;
            int row = slot >> 3;
            int kq = (slot & 7) << 2;
            fa[u] = *(const float4*)&A[(size_t)(m0 + row) * EMB + k0 + kq];
            fb[u] = *(const float4*)&B[(size_t)(n0 + row) * EMB + k0 + kq];
        }
    };

    auto store_stage = [&](int s) {
        const unsigned base = sb + (unsigned)s * STAGE_B;
#pragma unroll
        for (int u = 0; u < 4; u++) {
            int slot = tid + u * 256;
            int row = slot >> 3;
            int kq = (slot & 7) << 2;
            unsigned off = (unsigned)(row * ROW_B + kq * 4);
            unsigned h0, h1, h2, h3, l0, l1, l2, l3;
            tf32split(fa[u].x, h0, l0); tf32split(fa[u].y, h1, l1);
            tf32split(fa[u].z, h2, l2); tf32split(fa[u].w, h3, l3);
            STS_V4(base + off, h0, h1, h2, h3);
            STS_V4(base + TILE_B + off, l0, l1, l2, l3);
            tf32split(fb[u].x, h0, l0); tf32split(fb[u].y, h1, l1);
            tf32split(fb[u].z, h2, l2); tf32split(fb[u].w, h3, l3);
            STS_V4(base + 2 * TILE_B + off, h0, h1, h2, h3);
            STS_V4(base + 3 * TILE_B + off, l0, l1, l2, l3);
        }
    };

    const unsigned a_rl = (unsigned)((lane & 7) + ((lane >> 3) & 1) * 8);
    const unsigned a_by = (unsigned)((lane >> 4) * 16);
    const unsigned b_rl = (unsigned)(lane & 7);
    const unsigned b_by = (unsigned)(((lane >> 3) & 1) * 16);

    fetch(0);
    store_stage(0);
    fetch(1);

#pragma unroll 1
    for (int c = 0; c < NCH; c++) {
        __syncthreads();
        if (c + 1 < NCH) store_stage((c + 1) & 1);
        if (c + 2 < NCH) fetch(c + 2);

        const unsigned abase = sb + (unsigned)(c & 1) * STAGE_B;
        const unsigned bbase = abase + 2 * TILE_B;

#pragma unroll
        for (int k8 = 0; k8 < 4; k8++) {
            const unsigned koff = (unsigned)(k8 * 32);
            unsigned Ah[4][4], Al[4][4], Bh[4][2], Bl[4][2];
#pragma unroll
            for (int mt = 0; mt < 4; mt++) {
                unsigned ad = abase + (wm * 64 + mt * 16 + a_rl) * ROW_B + a_by + koff;
                LDSM_X4(Ah[mt][0], Ah[mt][1], Ah[mt][2], Ah[mt][3], ad);
                LDSM_X4(Al[mt][0], Al[mt][1], Al[mt][2], Al[mt][3], ad + TILE_B);
            }
#pragma unroll
            for (int nt = 0; nt < 4; nt++) {
                unsigned bd = bbase + (wn * 32 + nt * 8 + b_rl) * ROW_B + b_by + koff;
                LDSM_X2(Bh[nt][0], Bh[nt][1], bd);
                LDSM_X2(Bl[nt][0], Bl[nt][1], bd + TILE_B);
            }
#pragma unroll
            for (int mt = 0; mt < 4; mt++)
#pragma unroll
                for (int nt = 0; nt < 4; nt++) {
                    float* cc = acc[mt][nt];
                    MMA_TF32(cc[0], cc[1], cc[2], cc[3],
                             Ah[mt][0], Ah[mt][1], Ah[mt][2], Ah[mt][3],
                             Bh[nt][0], Bh[nt][1]);
                    MMA_TF32(cc[0], cc[1], cc[2], cc[3],
                             Ah[mt][0], Ah[mt][1], Ah[mt][2], Ah[mt][3],
                             Bl[nt][0], Bl[nt][1]);
                    MMA_TF32(cc[0], cc[1], cc[2], cc[3],
                             Al[mt][0], Al[mt][1], Al[mt][2], Al[mt][3],
                             Bh[nt][0], Bh[nt][1]);
                }
        }
    }

    const int g = lane >> 2;
    const int c2 = (lane & 3) * 2;
#pragma unroll
    for (int mt = 0; mt < 4; mt++) {
        const int r0 = m0 + wm * 64 + mt * 16 + g;
#pragma unroll
        for (int nt = 0; nt < 4; nt++) {
            const int col = n0 + wn * 32 + nt * 8 + c2;
            float2 bv = *(const float2*)&bias[col];
            float2 o0, o1;
            o0.x = (acc[mt][nt][0] + bv.x) * scale;
            o0.y = (acc[mt][nt][1] + bv.y) * scale;
            o1.x = (acc[mt][nt][2] + bv.x) * scale;
            o1.y = (acc[mt][nt][3] + bv.y) * scale;
            *(float2*)&C[(size_t)r0 * EMB + col] = o0;
            *(float2*)&C[(size_t)(r0 + 8) * EMB + col] = o1;
        }
    }
}

// ---------------------------------------------------------------------------
// fp32 SIMT GEMM (VERIFIED round 2) — K and V projections only
// (downstream QuotRem quantizer is hypersensitive: must stay fp32-exact).
// ---------------------------------------------------------------------------
#define BM 128
#define BN 128
#define BK 16
#define GK 2048

__global__ __launch_bounds__(256) void gemm_nt_kernel(
    const float* __restrict__ A, const float* __restrict__ B,
    const float* __restrict__ bias, float* __restrict__ C, float scale)
{
    __shared__ float As[BK][BM];
    __shared__ float Bs[BK][BN];

    const int tid = threadIdx.x;
    const int tx = tid & 15;
    const int ty = tid >> 4;
    const int m0 = blockIdx.y * BM;
    const int n0 = blockIdx.x * BN;

    float acc[8][8];
#pragma unroll
    for (int i = 0; i < 8; i++)
#pragma unroll
        for (int j = 0; j < 8; j++) acc[i][j] = 0.f;

    for (int kt = 0; kt < GK; kt += BK) {
#pragma unroll
        for (int u = 0; u < 2; u++) {
            int i = tid + u * 256;
            int row = i >> 2;
            int kq = (i & 3) << 2;
            float4 a = *(const float4*)&A[(size_t)(m0 + row) * GK + kt + kq];
            As[kq + 0][row] = a.x; As[kq + 1][row] = a.y;
            As[kq + 2][row] = a.z; As[kq + 3][row] = a.w;
            float4 b = *(const float4*)&B[(size_t)(n0 + row) * GK + kt + kq];
            Bs[kq + 0][row] = b.x; Bs[kq + 1][row] = b.y;
            Bs[kq + 2][row] = b.z; Bs[kq + 3][row] = b.w;
        }
        __syncthreads();

#pragma unroll
        for (int k = 0; k < BK; k++) {
            float4 a0 = *(const float4*)&As[k][ty * 8];
            float4 a1 = *(const float4*)&As[k][ty * 8 + 4];
            float4 b0 = *(const float4*)&Bs[k][tx * 8];
            float4 b1 = *(const float4*)&Bs[k][tx * 8 + 4];
            float ar[8] = {a0.x, a0.y, a0.z, a0.w, a1.x, a1.y, a1.z, a1.w};
            float br[8] = {b0.x, b0.y, b0.z, b0.w, b1.x, b1.y, b1.z, b1.w};
#pragma unroll
            for (int i = 0; i < 8; i++)
#pragma unroll
                for (int j = 0; j < 8; j++)
                    acc[i][j] += ar[i] * br[j];
        }
        __syncthreads();
    }

    float4 bv0 = *(const float4*)&bias[n0 + tx * 8];
    float4 bv1 = *(const float4*)&bias[n0 + tx * 8 + 4];
    float bb[8] = {bv0.x, bv0.y, bv0.z, bv0.w, bv1.x, bv1.y, bv1.z, bv1.w};

#pragma unroll
    for (int i = 0; i < 8; i++) {
        int row = m0 + ty * 8 + i;
        float4 o0, o1;
        o0.x = (acc[i][0] + bb[0]) * scale;
        o0.y = (acc[i][1] + bb[1]) * scale;
        o0.z = (acc[i][2] + bb[2]) * scale;
        o0.w = (acc[i][3] + bb[3]) * scale;
        o1.x = (acc[i][4] + bb[4]) * scale;
        o1.y = (acc[i][5] + bb[5]) * scale;
        o1.z = (acc[i][6] + bb[6]) * scale;
        o1.w = (acc[i][7] + bb[7]) * scale;
        *(float4*)&C[(size_t)row * GK + n0 + tx * 8] = o0;
        *(float4*)&C[(size_t)row * GK + n0 + tx * 8 + 4] = o1;
    }
}

// ---------------------------------------------------------------------------
// QuotRem fake quantize (verified)
// ---------------------------------------------------------------------------
__global__ __launch_bounds__(256) void quotrem_quantize_kernel(float* __restrict__ X)
{
    const int g = blockIdx.x * blockDim.x + threadIdx.x;
    if (g >= (SEQ * EMB) / 16) return;

    float4* p = (float4*)(X + (size_t)g * 16);
    float4 a = p[0], b = p[1], c = p[2], d = p[3];
    float x[16] = {a.x, a.y, a.z, a.w, b.x, b.y, b.z, b.w,
                   c.x, c.y, c.z, c.w, d.x, d.y, d.z, d.w};

    float mx = x[0], mn = x[0];
#pragma unroll
    for (int i = 1; i < 16; i++) {
        mx = fmaxf(mx, x[i]);
        mn = fminf(mn, x[i]);
    }
    float ma = fmaxf(fmaxf(mx, -mn), 1e-8f);

    float l2 = log2f(ma);
    float bflo = exp2f(floorf(l2));
    float bcei = exp2f(ceilf(l2));
    float base = (fabsf(ma - bflo) <= fabsf(bcei - ma)) ? bflo : bcei;
    base = fminf(fmaxf(base, 1.0f), 128.0f);

    float sign = (fabsf(mx) >= fabsf(mn)) ? 1.0f : -1.0f;
    float hb = 0.5f * base;
    float sb = sign * base;

    float qs[16], r[16];
    float mar = 0.f;
#pragma unroll
    for (int i = 0; i < 16; i++) {
        float q = (x[i] * sign >= hb) ? 1.0f : 0.0f;
        qs[i] = q * sb;
        r[i] = x[i] - qs[i];
        mar = fmaxf(mar, fabsf(r[i]));
    }
    mar = fmaxf(mar, 1e-8f);
    float sr = mar * (1.0f / 3.0f);

#pragma unroll
    for (int i = 0; i < 16; i++) {
        float rq = rintf(r[i] / sr);
        rq = fminf(fmaxf(rq, -4.0f), 3.0f);
        x[i] = qs[i] + rq * sr;
    }

    a.x = x[0];  a.y = x[1];  a.z = x[2];  a.w = x[3];
    b.x = x[4];  b.y = x[5];  b.z = x[6];  b.w = x[7];
    c.x = x[8];  c.y = x[9];  c.z = x[10]; c.w = x[11];
    d.x = x[12]; d.y = x[13]; d.z = x[14]; d.w = x[15];
    p[0] = a; p[1] = b; p[2] = c; p[3] = d;
}

// ---------------------------------------------------------------------------
// MMA causal flash attention.
// CTA = (128 q-rows, 1 head), 8 warps, warp = 16 q-rows. Key tiles of 64.
// Q*K^T via bf16x3 (Qhi*Khi + Qhi*Klo + Qlo*Khi) — scores exact to ~2e-5 abs.
// P*V via (Phi*Vhi + Phi*Vlo + Plo*Vhi). P repacked accumulator->A-frag in regs.
// SMEM stage = Khi|Klo|Vhi|Vlo, 64 rows x 144B each; 2 stages, single-sync DB.
// ---------------------------------------------------------------------------
#define FA_ROW 144
#define FA_TILE (64 * FA_ROW)           // 9216
#define FA_STAGE (4 * FA_TILE)          // 36864
#define FA_SMEM (2 * FA_STAGE)          // 73728

__global__ __launch_bounds__(256, 1)
void flash_attn_mma_kernel(const float* __restrict__ Q, const float* __restrict__ K,
                           const float* __restrict__ V, float* __restrict__ O)
{
    extern __shared__ char smem[];
    const unsigned sb = s2u(smem);
    const int tid = threadIdx.x;
    const int wid = tid >> 5;
    const int lane = tid & 31;
    const int head = blockIdx.y;
    const int bx = (int)gridDim.x - 1 - (int)blockIdx.x;   // heavy blocks first
    const int r0 = bx * 128;
    const int hb = head * HDIM;
    const int rw = r0 + wid * 16;
    const int g = lane >> 2;
    const int t = lane & 3;

    // ---- stage Q (128x64) into SMEM as bf16 hi/lo, then to A-fragments ----
#pragma unroll
    for (int u = 0; u < 8; u++) {
        int slot = tid + u * 256;
        int row = slot >> 4;
        int dq = (slot & 15) << 2;
        float4 v = *(const float4*)&Q[(size_t)(r0 + row) * EMB + hb + dq];
        unsigned h01, l01, h23, l23;
        split2(v.x, v.y, h01, l01);
        split2(v.z, v.w, h23, l23);
        unsigned off = (unsigned)(row * FA_ROW + dq * 2);
        STS_V2(sb + off, h01, h23);
        STS_V2(sb + 18432u + off, l01, l23);
    }
    __syncthreads();

    const unsigned a_rl = (unsigned)((lane & 7) + ((lane >> 3) & 1) * 8);
    const unsigned a_by = (unsigned)((lane >> 4) * 16);
    unsigned QH[4][4], QL[4][4];
#pragma unroll
    for (int kc = 0; kc < 4; kc++) {
        unsigned ad = sb + (wid * 16 + a_rl) * FA_ROW + kc * 32 + a_by;
        LDSM_X4(QH[kc][0], QH[kc][1], QH[kc][2], QH[kc][3], ad);
        LDSM_X4(QL[kc][0], QL[kc][1], QL[kc][2], QL[kc][3], ad + 18432u);
    }
    __syncthreads();

    float o[8][4];
#pragma unroll
    for (int j = 0; j < 8; j++)
#pragma unroll
        for (int r = 0; r < 4; r++) o[j][r] = 0.f;
    float m0r = -1e30f, m1r = -1e30f, l0 = 0.f, l1 = 0.f;

    const int ntiles = 2 * bx + 2;
    float4 fk[4], fv[4];

    auto fetchKV = [&](int tI) {
        const int c0 = tI * 64;
#pragma unroll
        for (int u = 0; u < 4; u++) {
            int slot = tid + u * 256;
            int kr = slot >> 4;
            int dq = (slot & 15) << 2;
            fk[u] = *(const float4*)&K[(size_t)(c0 + kr) * EMB + hb + dq];
            fv[u] = *(const float4*)&V[(size_t)(c0 + kr) * EMB + hb + dq];
        }
    };
    auto storeKV = [&](int s) {
        const unsigned base = sb + (unsigned)s * FA_STAGE;
#pragma unroll
        for (int u = 0; u < 4; u++) {
            int slot = tid + u * 256;
            int kr = slot >> 4;
            int dq = (slot & 15) << 2;
            unsigned off = (unsigned)(kr * FA_ROW + dq * 2);
            unsigned h01, l01, h23, l23;
            split2(fk[u].x, fk[u].y, h01, l01);
            split2(fk[u].z, fk[u].w, h23, l23);
            STS_V2(base + off, h01, h23);
            STS_V2(base + FA_TILE + off, l01, l23);
            split2(fv[u].x, fv[u].y, h01, l01);
            split2(fv[u].z, fv[u].w, h23, l23);
            STS_V2(base + 2 * FA_TILE + off, h01, h23);
            STS_V2(base + 3 * FA_TILE + off, l01, l23);
        }
    };

    fetchKV(0);
    storeKV(0);
    if (ntiles > 1) fetchKV(1);

#pragma unroll 1
    for (int c = 0; c < ntiles; c++) {
        __syncthreads();
        if (c + 1 < ntiles) storeKV((c + 1) & 1);
        if (c + 2 < ntiles) fetchKV(c + 2);

        const int c0 = c * 64;
        if (c0 <= rw + 15) {                  // warp has visible keys in tile
            const unsigned kb = sb + (unsigned)(c & 1) * FA_STAGE;

            float s[8][4];
#pragma unroll
            for (int j = 0; j < 8; j++)
#pragma unroll
                for (int r = 0; r < 4; r++) s[j][r] = 0.f;

#pragma unroll
            for (int j = 0; j < 8; j++) {
                const unsigned bd = kb + (8 * j + (lane & 7)) * FA_ROW
                                  + ((lane >> 3) & 1) * 16;
#pragma unroll
                for (int kc = 0; kc < 4; kc++) {
                    unsigned bh0, bh1, bl0, bl1;
                    LDSM_X2(bh0, bh1, bd + kc * 32);
                    LDSM_X2(bl0, bl1, bd + kc * 32 + FA_TILE);
                    MMA_BF16(s[j][0], s[j][1], s[j][2], s[j][3],
                             QH[kc][0], QH[kc][1], QH[kc][2], QH[kc][3], bh0, bh1);
                    MMA_BF16(s[j][0], s[j][1], s[j][2], s[j][3],
                             QH[kc][0], QH[kc][1], QH[kc][2], QH[kc][3], bl0, bl1);
                    MMA_BF16(s[j][0], s[j][1], s[j][2], s[j][3],
                             QL[kc][0], QL[kc][1], QL[kc][2], QL[kc][3], bh0, bh1);
                }
            }

            // causal mask (only near the diagonal)
            if (c0 + 63 > rw) {
                const int rA = rw + g;
                const int rB = rw + g + 8;
#pragma unroll
                for (int j = 0; j < 8; j++) {
                    int col = c0 + 8 * j + 2 * t;
                    if (col > rA)     s[j][0] = -1e30f;
                    if (col + 1 > rA) s[j][1] = -1e30f;
                    if (col > rB)     s[j][2] = -1e30f;
                    if (col + 1 > rB) s[j][3] = -1e30f;
                }
            }

            // online softmax (rows rA: regs 0,1 ; rows rB: regs 2,3)
            float t0 = -1e30f, t1 = -1e30f;
#pragma unroll
            for (int j = 0; j < 8; j++) {
                t0 = fmaxf(t0, fmaxf(s[j][0], s[j][1]));
                t1 = fmaxf(t1, fmaxf(s[j][2], s[j][3]));
            }
            t0 = fmaxf(t0, __shfl_xor_sync(0xffffffff, t0, 1));
            t0 = fmaxf(t0, __shfl_xor_sync(0xffffffff, t0, 2));
            t1 = fmaxf(t1, __shfl_xor_sync(0xffffffff, t1, 1));
            t1 = fmaxf(t1, __shfl_xor_sync(0xffffffff, t1, 2));
            const float mn0 = fmaxf(m0r, t0);
            const float mn1 = fmaxf(m1r, t1);
            const float sc0 = __expf(m0r - mn0);
            const float sc1 = __expf(m1r - mn1);
            float sum0 = 0.f, sum1 = 0.f;
#pragma unroll
            for (int j = 0; j < 8; j++) {
                float p0 = __expf(s[j][0] - mn0);
                float p1 = __expf(s[j][1] - mn0);
                float p2 = __expf(s[j][2] - mn1);
                float p3 = __expf(s[j][3] - mn1);
                s[j][0] = p0; s[j][1] = p1; s[j][2] = p2; s[j][3] = p3;
                sum0 += p0 + p1;
                sum1 += p2 + p3;
            }
            sum0 += __shfl_xor_sync(0xffffffff, sum0, 1);
            sum0 += __shfl_xor_sync(0xffffffff, sum0, 2);
            sum1 += __shfl_xor_sync(0xffffffff, sum1, 1);
            sum1 += __shfl_xor_sync(0xffffffff, sum1, 2);
            l0 = l0 * sc0 + sum0;
            l1 = l1 * sc1 + sum1;
            m0r = mn0; m1r = mn1;
#pragma unroll
            for (int j = 0; j < 8; j++) {
                o[j][0] *= sc0; o[j][1] *= sc0;
                o[j][2] *= sc1; o[j][3] *= sc1;
            }

            // P*V : P accumulator -> bf16 hi/lo A-fragments in registers
#pragma unroll
            for (int kc2 = 0; kc2 < 4; kc2++) {
                unsigned ph[4], pl[4];
                split2(s[2 * kc2][0],     s[2 * kc2][1],     ph[0], pl[0]);
                split2(s[2 * kc2][2],     s[2 * kc2][3],     ph[1], pl[1]);
                split2(s[2 * kc2 + 1][0], s[2 * kc2 + 1][1], ph[2], pl[2]);
                split2(s[2 * kc2 + 1][2], s[2 * kc2 + 1][3], ph[3], pl[3]);
                const unsigned vrow = kb + 2 * FA_TILE
                                    + (16 * kc2 + (lane & 15)) * FA_ROW;
#pragma unroll
                for (int j = 0; j < 8; j++) {
                    unsigned v0, v1, w0, w1;
                    LDSM_X2_T(v0, v1, vrow + j * 16);
                    LDSM_X2_T(w0, w1, vrow + j * 16 + FA_TILE);
                    MMA_BF16(o[j][0], o[j][1], o[j][2], o[j][3],
                             ph[0], ph[1], ph[2], ph[3], v0, v1);
                    MMA_BF16(o[j][0], o[j][1], o[j][2], o[j][3],
                             ph[0], ph[1], ph[2], ph[3], w0, w1);
                    MMA_BF16(o[j][0], o[j][1], o[j][2], o[j][3],
                             pl[0], pl[1], pl[2], pl[3], v0, v1);
                }
            }
        }
    }

    // normalize and write
    const float inv0 = 1.0f / l0;
    const float inv1 = 1.0f / l1;
    const int rA = rw + g;
    const int rB = rw + g + 8;
#pragma unroll
    for (int j = 0; j < 8; j++) {
        const int col = hb + 8 * j + 2 * t;
        float2 oa, ob;
        oa.x = o[j][0] * inv0; oa.y = o[j][1] * inv0;
        ob.x = o[j][2] * inv1; ob.y = o[j][3] * inv1;
        *(float2*)&O[(size_t)rA * EMB + col] = oa;
        *(float2*)&O[(size_t)rB * EMB + col] = ob;
    }
}

// ---------------------------------------------------------------------------
// Launch
// ---------------------------------------------------------------------------
extern "C" void kernel_launch(void* const* d_in, const int* in_sizes, int n_in,
                              void* d_out, int out_size)
{
    const float* X  = (const float*)d_in[0];
    const float* Wq = (const float*)d_in[1];
    const float* bq = (const float*)d_in[2];
    const float* Wk = (const float*)d_in[3];
    const float* bk = (const float*)d_in[4];
    const float* Wv = (const float*)d_in[5];
    const float* bv = (const float*)d_in[6];
    const float* Wo = (const float*)d_in[7];
    const float* bo = (const float*)d_in[8];
    float* out = (float*)d_out;

    void *pQ, *pK, *pV, *pO;
    cudaGetSymbolAddress(&pQ, g_Q);
    cudaGetSymbolAddress(&pK, g_K);
    cudaGetSymbolAddress(&pV, g_V);
    cudaGetSymbolAddress(&pO, g_O);
    float* Qb = (float*)pQ;
    float* Kb = (float*)pK;
    float* Vb = (float*)pV;
    float* Ob = (float*)pO;

    cudaFuncSetAttribute(gemm_mma_kernel,
                         cudaFuncAttributeMaxDynamicSharedMemorySize, GEMM_SMEM);
    cudaFuncSetAttribute(flash_attn_mma_kernel,
                         cudaFuncAttributeMaxDynamicSharedMemorySize, FA_SMEM);

    dim3 gg(EMB / 128, SEQ / 128);

    // Q projection: tf32-mma (verified)
    gemm_mma_kernel<<<gg, 256, GEMM_SMEM>>>(X, Wq, bq, Qb, SCALING);
    // K, V projections: exact fp32 (quantizer-sensitive)
    gemm_nt_kernel<<<gg, 256>>>(X, Wk, bk, Kb, 1.0f);
    gemm_nt_kernel<<<gg, 256>>>(X, Wv, bv, Vb, 1.0f);

    const int ngroups = (SEQ * EMB) / 16;
    quotrem_quantize_kernel<<<ngroups / 256, 256>>>(Kb);
    quotrem_quantize_kernel<<<ngroups / 256, 256>>>(Vb);

    flash_attn_mma_kernel<<<dim3(SEQ / 128, NHEAD), 256, FA_SMEM>>>(Qb, Kb, Vb, Ob);

    // Output projection: tf32-mma (verified)
    gemm_mma_kernel<<<gg, 256, GEMM_SMEM>>>(Ob, Wo, bo, out, 1.0f);
}